// round 13
// baseline (speedup 1.0000x reference)
#include <cuda_runtime.h>
#include <cuda_bf16.h>
#include <cuda_fp16.h>
#include <cstdint>

#define Nn   100000
#define Ee   1600000
#define Bb   64
#define DINc 9
#define Hh   128
#define EPSv 1e-5f
#define NBLK 98          // ceil(Nn/1024)

// ---------------- device scratch ----------------
__device__ __half   g_hh [Nn * Hh];
__device__ uint32_t g_hp0[Nn * Hh];
__device__ uint32_t g_hp1[Nn * Hh];
__device__ uint32_t g_agp[Nn * Hh];
__device__ uint4    g_wfrag[3 * 8192];
__device__ int      g_deg[Nn];          // zero-on-entry (cleaned by k_agg)
__device__ int      g_rowptr[Nn + 1];
__device__ int      g_rowfill[Nn];      // zero-on-entry (cleaned by k_agg)
__device__ int      g_col[Ee];
__device__ int      g_chainval[NBLK];
__device__ int      g_chainflag[NBLK];  // zero-on-entry (cleaned by k_agg)
__device__ int      g_done;             // zero-on-entry (cleaned by k_agg)
__device__ float    g_psum[Bb * Hh];    // zero-on-entry (cleaned by k_pool_fin)
__device__ int      g_pmax[Bb * Hh];
__device__ int      g_pcnt[Bb];

// ---------------- helpers ----------------
__device__ __forceinline__ uint32_t packf(float v) {
    __nv_bfloat16 hb = __float2bfloat16(v);
    __nv_bfloat16 lb = __float2bfloat16(v - __bfloat162float(hb));
    return ((uint32_t)__bfloat16_as_ushort(hb) << 16) | (uint32_t)__bfloat16_as_ushort(lb);
}
__device__ __forceinline__ uint32_t pack_bf16(__nv_bfloat16 a, __nv_bfloat16 b) {
    return (uint32_t)__bfloat16_as_ushort(a) | ((uint32_t)__bfloat16_as_ushort(b) << 16);
}
__device__ __forceinline__ void mma16816(float* d, const uint32_t* a, uint32_t b0, uint32_t b1) {
    asm volatile("mma.sync.aligned.m16n8k16.row.col.f32.bf16.bf16.f32 "
        "{%0,%1,%2,%3}, {%4,%5,%6,%7}, {%8,%9}, {%0,%1,%2,%3};"
        : "+f"(d[0]), "+f"(d[1]), "+f"(d[2]), "+f"(d[3])
        : "r"(a[0]), "r"(a[1]), "r"(a[2]), "r"(a[3]), "r"(b0), "r"(b1));
}
__device__ __forceinline__ void acc_h4(float4& a, uint2 u) {
    __half2 p0 = *reinterpret_cast<const __half2*>(&u.x);
    __half2 p1 = *reinterpret_cast<const __half2*>(&u.y);
    float2 f0 = __half22float2(p0);
    float2 f1 = __half22float2(p1);
    a.x += f0.x; a.y += f0.y; a.z += f1.x; a.w += f1.y;
}

// ---------------- launch 1: fused embed + degree-count + weight-prep ----------------
#define PRE_DEG_BLKS  (Ee / 128)           // 12500
#define PRE_W_BLKS    (3 * 8192 / 128)     // 192
#define PRE_GRID      (Nn + PRE_DEG_BLKS + PRE_W_BLKS)

__global__ void k_pre(const float* __restrict__ x, const float* __restrict__ W0,
                      const float* __restrict__ b0, const float* __restrict__ g0,
                      const float* __restrict__ be0, uint32_t* __restrict__ hp,
                      const int* __restrict__ edge,
                      const float* __restrict__ Wl1, const float* __restrict__ Wr1,
                      const float* __restrict__ Wl2, const float* __restrict__ Wr2,
                      const float* __restrict__ Wl3, const float* __restrict__ Wr3) {
    int b = blockIdx.x;
    int t = threadIdx.x;

    if (b >= Nn) {
        int rb = b - Nn;
        if (rb < PRE_DEG_BLKS) {
            int e = rb * 128 + t;
            atomicAdd(&g_deg[edge[Ee + e]], 1);   // g_deg zeroed by prior pass's k_agg
        } else {
            int idx = (rb - PRE_DEG_BLKS) * 128 + t;
            int L = idx >> 13, id = idx & 8191;
            const float* Wl = (L == 0) ? Wl1 : (L == 1) ? Wl2 : Wl3;
            const float* Wr = (L == 0) ? Wr1 : (L == 1) ? Wr2 : Wr3;
            int lane = id & 31, ks = (id >> 5) & 15, nt = id >> 9;
            int o = nt * 8 + (lane >> 2);
            int kb = ks * 16 + 2 * (lane & 3);
            float v[4];
#pragma unroll
            for (int j = 0; j < 4; j++) {
                int k = kb + (j >> 1) * 8 + (j & 1);
                v[j] = (k < Hh) ? Wl[o * Hh + k] : Wr[o * Hh + (k - Hh)];
            }
            __nv_bfloat16 hb[4]; __nv_bfloat16 lb[4];
#pragma unroll
            for (int j = 0; j < 4; j++) {
                hb[j] = __float2bfloat16(v[j]);
                lb[j] = __float2bfloat16(v[j] - __bfloat162float(hb[j]));
            }
            uint4 q;
            q.x = pack_bf16(hb[0], hb[1]);
            q.y = pack_bf16(hb[2], hb[3]);
            q.z = pack_bf16(lb[0], lb[1]);
            q.w = pack_bf16(lb[2], lb[3]);
            g_wfrag[idx] = q;
        }
        return;
    }

    // embed: node b, channel t
    int n = b, o = t;
    __shared__ float sx[DINc];
    if (o < DINc) sx[o] = x[n * DINc + o];
    __syncthreads();
    float acc = b0[o];
#pragma unroll
    for (int k = 0; k < DINc; k++) acc += W0[o * DINc + k] * sx[k];

    float s = acc, sq = acc * acc;
#pragma unroll
    for (int ofs = 16; ofs > 0; ofs >>= 1) {
        s  += __shfl_xor_sync(0xffffffffu, s,  ofs);
        sq += __shfl_xor_sync(0xffffffffu, sq, ofs);
    }
    __shared__ float rs[4], rq[4];
    int w = o >> 5, lane = o & 31;
    if (lane == 0) { rs[w] = s; rq[w] = sq; }
    __syncthreads();
    s  = rs[0] + rs[1] + rs[2] + rs[3];
    sq = rq[0] + rq[1] + rq[2] + rq[3];
    float mean = s * (1.f / Hh);
    float var  = sq * (1.f / Hh) - mean * mean;
    float rstd = rsqrtf(var + EPSv);
    float v = (acc - mean) * rstd * g0[o] + be0[o];
    float r = fmaxf(v, 0.f);
    size_t idx = (size_t)n * Hh + o;
    g_hh[idx] = __float2half_rn(r);
    hp[idx] = packf(r);
}

// ---------------- launch 2: scan (chained lookback) + barrier + CSR fill ----------------
__global__ void __launch_bounds__(1024, 1)
k_scanfill(const int* __restrict__ edge) {
    __shared__ int sh[1024];
    __shared__ int s_off;
    int t = threadIdx.x, b = blockIdx.x;
    int idx = b * 1024 + t;
    int v = (idx < Nn) ? g_deg[idx] : 0;
    sh[t] = v;
    for (int ofs = 1; ofs < 1024; ofs <<= 1) {
        __syncthreads();
        int add = (t >= ofs) ? sh[t - ofs] : 0;
        __syncthreads();
        sh[t] += add;
    }
    __syncthreads();
    // chained exclusive block offsets
    if (t == 1023) {
        int total = sh[1023];
        int prev = 0;
        if (b > 0) {
            while (atomicAdd(&g_chainflag[b - 1], 0) == 0) {}
            prev = g_chainval[b - 1];
        }
        g_chainval[b] = prev + total;
        __threadfence();
        atomicExch(&g_chainflag[b], 1);
        s_off = prev;
    }
    __syncthreads();
    int off = s_off;
    if (idx < Nn) g_rowptr[idx] = sh[t] - v + off;
    if (idx == Nn) g_rowptr[Nn] = Ee;

    // grid barrier: all rowptr writes visible before fill
    __threadfence();
    __syncthreads();
    if (t == 0) {
        atomicAdd(&g_done, 1);
        while (atomicAdd(&g_done, 0) < NBLK) {}
    }
    __syncthreads();
    __threadfence();

    // CSR fill
    for (int e = b * 1024 + t; e < Ee; e += NBLK * 1024) {
        int d = edge[Ee + e];
        int pos = g_rowptr[d] + atomicAdd(&g_rowfill[d], 1);
        g_col[pos] = edge[e];
    }
}

// ---------------- launch 3: mean aggregation (round-8 proven loop) + cleanup ----------------
__global__ void k_agg(const __half* __restrict__ hh, uint32_t* __restrict__ agp, int clean) {
    int gt = blockIdx.x * blockDim.x + threadIdx.x;
    if (clean) {
        if (gt < Nn) { g_deg[gt] = 0; g_rowfill[gt] = 0; }
        if (gt < NBLK) g_chainflag[gt] = 0;
        if (gt == 0) g_done = 0;
    }
    int gw   = gt >> 5;
    int lane = threadIdx.x & 31;
    if (gw >= Nn) return;
    int beg = g_rowptr[gw], end = g_rowptr[gw + 1];
    float4 aA = make_float4(0.f, 0.f, 0.f, 0.f);
    float4 aB = make_float4(0.f, 0.f, 0.f, 0.f);
    float4 aC = make_float4(0.f, 0.f, 0.f, 0.f);
    float4 aD = make_float4(0.f, 0.f, 0.f, 0.f);
    int e = beg;
    for (; e + 8 <= end; e += 8) {
        int s0 = __ldg(&g_col[e]);
        int s1 = __ldg(&g_col[e + 1]);
        int s2 = __ldg(&g_col[e + 2]);
        int s3 = __ldg(&g_col[e + 3]);
        int s4 = __ldg(&g_col[e + 4]);
        int s5 = __ldg(&g_col[e + 5]);
        int s6 = __ldg(&g_col[e + 6]);
        int s7 = __ldg(&g_col[e + 7]);
        uint2 u0 = __ldg((const uint2*)(hh + (size_t)s0 * Hh) + lane);
        uint2 u1 = __ldg((const uint2*)(hh + (size_t)s1 * Hh) + lane);
        uint2 u2 = __ldg((const uint2*)(hh + (size_t)s2 * Hh) + lane);
        uint2 u3 = __ldg((const uint2*)(hh + (size_t)s3 * Hh) + lane);
        uint2 u4 = __ldg((const uint2*)(hh + (size_t)s4 * Hh) + lane);
        uint2 u5 = __ldg((const uint2*)(hh + (size_t)s5 * Hh) + lane);
        uint2 u6 = __ldg((const uint2*)(hh + (size_t)s6 * Hh) + lane);
        uint2 u7 = __ldg((const uint2*)(hh + (size_t)s7 * Hh) + lane);
        acc_h4(aA, u0); acc_h4(aB, u1); acc_h4(aC, u2); acc_h4(aD, u3);
        acc_h4(aA, u4); acc_h4(aB, u5); acc_h4(aC, u6); acc_h4(aD, u7);
    }
    for (; e + 4 <= end; e += 4) {
        int s0 = __ldg(&g_col[e]);
        int s1 = __ldg(&g_col[e + 1]);
        int s2 = __ldg(&g_col[e + 2]);
        int s3 = __ldg(&g_col[e + 3]);
        uint2 u0 = __ldg((const uint2*)(hh + (size_t)s0 * Hh) + lane);
        uint2 u1 = __ldg((const uint2*)(hh + (size_t)s1 * Hh) + lane);
        uint2 u2 = __ldg((const uint2*)(hh + (size_t)s2 * Hh) + lane);
        uint2 u3 = __ldg((const uint2*)(hh + (size_t)s3 * Hh) + lane);
        acc_h4(aA, u0); acc_h4(aB, u1); acc_h4(aC, u2); acc_h4(aD, u3);
    }
    for (; e < end; e++) {
        int s = __ldg(&g_col[e]);
        uint2 u = __ldg((const uint2*)(hh + (size_t)s * Hh) + lane);
        acc_h4(aA, u);
    }
    float inv = 1.0f / fmaxf((float)(end - beg), 1.0f);
    uint4 q;
    q.x = packf((aA.x + aB.x + aC.x + aD.x) * inv);
    q.y = packf((aA.y + aB.y + aC.y + aD.y) * inv);
    q.z = packf((aA.z + aB.z + aC.z + aD.z) * inv);
    q.w = packf((aA.w + aB.w + aC.w + aD.w) * inv);
    ((uint4*)(agp + (size_t)gw * Hh))[lane] = q;
}

// ---------------- launch 4 (PROFILED): mma.sync fused dual GEMM + LN + ReLU ----------------
#define GSMEM (8192 * 16 + 3 * 512)

__global__ void __launch_bounds__(512, 1)
k_gemm_mma(const uint32_t* __restrict__ agp, const uint32_t* __restrict__ hp,
           const uint4* __restrict__ wfrag,
           const float* __restrict__ bl, const float* __restrict__ gg,
           const float* __restrict__ bb,
           __half* __restrict__ hh_out, uint32_t* __restrict__ hp_out,
           float* __restrict__ f32_out, int mode)
{
    extern __shared__ char smc[];
    uint4* sB    = (uint4*)smc;
    float* sBias = (float*)(smc + 8192 * 16);
    float* sG    = sBias + 128;
    float* sBb   = sG + 128;

    int tid = threadIdx.x, lane = tid & 31, warp = tid >> 5;
    int nb = blockIdx.x * 256;

#pragma unroll
    for (int i = 0; i < 16; i++) sB[tid + i * 512] = wfrag[tid + i * 512];
    if (tid < 128) { sBias[tid] = bl[tid]; sG[tid] = gg[tid]; sBb[tid] = bb[tid]; }
    __syncthreads();

    int r0    = warp * 16 + (lane >> 2);
    int grow0 = nb + r0, grow1 = grow0 + 8;
    bool v0 = grow0 < Nn, v1 = grow1 < Nn;
    int kcol = 2 * (lane & 3);

    float acc[16][4];
#pragma unroll
    for (int nt = 0; nt < 16; nt++) {
        acc[nt][0] = 0.f; acc[nt][1] = 0.f; acc[nt][2] = 0.f; acc[nt][3] = 0.f;
    }

    const uint2 z2 = make_uint2(0u, 0u);
#pragma unroll 4
    for (int ks = 0; ks < 16; ks++) {
        const uint32_t* pp = (ks < 8) ? agp : hp;
        int ko = (ks & 7) * 16 + kcol;
        const uint32_t* r0p = pp + (size_t)grow0 * Hh + ko;
        const uint32_t* r1p = pp + (size_t)grow1 * Hh + ko;
        uint2 p00 = v0 ? __ldg((const uint2*)r0p)       : z2;
        uint2 p02 = v0 ? __ldg((const uint2*)(r0p + 8)) : z2;
        uint2 p10 = v1 ? __ldg((const uint2*)r1p)       : z2;
        uint2 p12 = v1 ? __ldg((const uint2*)(r1p + 8)) : z2;
        uint32_t ah[4], al[4];
        ah[0] = __byte_perm(p00.x, p00.y, 0x7632); al[0] = __byte_perm(p00.x, p00.y, 0x5410);
        ah[1] = __byte_perm(p10.x, p10.y, 0x7632); al[1] = __byte_perm(p10.x, p10.y, 0x5410);
        ah[2] = __byte_perm(p02.x, p02.y, 0x7632); al[2] = __byte_perm(p02.x, p02.y, 0x5410);
        ah[3] = __byte_perm(p12.x, p12.y, 0x7632); al[3] = __byte_perm(p12.x, p12.y, 0x5410);
        const uint4* brow = sB + ks * 32 + lane;
#pragma unroll
        for (int nt = 0; nt < 16; nt++) {
            uint4 b = brow[nt * 512];
            mma16816(acc[nt], ah, b.x, b.y);
            mma16816(acc[nt], al, b.x, b.y);
            mma16816(acc[nt], ah, b.z, b.w);
        }
    }

    float s0 = 0.f, q0 = 0.f, s1 = 0.f, q1 = 0.f;
#pragma unroll
    for (int nt = 0; nt < 16; nt++) {
        int c = nt * 8 + kcol;
        float b0v = sBias[c], b1v = sBias[c + 1];
        acc[nt][0] += b0v; acc[nt][1] += b1v;
        acc[nt][2] += b0v; acc[nt][3] += b1v;
        s0 += acc[nt][0] + acc[nt][1];
        q0 += acc[nt][0] * acc[nt][0] + acc[nt][1] * acc[nt][1];
        s1 += acc[nt][2] + acc[nt][3];
        q1 += acc[nt][2] * acc[nt][2] + acc[nt][3] * acc[nt][3];
    }
#pragma unroll
    for (int ofs = 1; ofs <= 2; ofs <<= 1) {
        s0 += __shfl_xor_sync(0xffffffffu, s0, ofs);
        q0 += __shfl_xor_sync(0xffffffffu, q0, ofs);
        s1 += __shfl_xor_sync(0xffffffffu, s1, ofs);
        q1 += __shfl_xor_sync(0xffffffffu, q1, ofs);
    }
    float mean0 = s0 * (1.f / Hh);
    float rstd0 = rsqrtf(q0 * (1.f / Hh) - mean0 * mean0 + EPSv);
    float mean1 = s1 * (1.f / Hh);
    float rstd1 = rsqrtf(q1 * (1.f / Hh) - mean1 * mean1 + EPSv);

#pragma unroll
    for (int nt = 0; nt < 16; nt++) {
        int c = nt * 8 + kcol;
        float gc0 = sG[c], gc1 = sG[c + 1], bc0 = sBb[c], bc1 = sBb[c + 1];
        float w0 = fmaxf((acc[nt][0] - mean0) * rstd0 * gc0 + bc0, 0.f);
        float w1 = fmaxf((acc[nt][1] - mean0) * rstd0 * gc1 + bc1, 0.f);
        float w2 = fmaxf((acc[nt][2] - mean1) * rstd1 * gc0 + bc0, 0.f);
        float w3 = fmaxf((acc[nt][3] - mean1) * rstd1 * gc1 + bc1, 0.f);
        if (mode == 0) {
            if (v0) {
                __half2 hw; hw.x = __float2half_rn(w0); hw.y = __float2half_rn(w1);
                *(__half2*)(hh_out + (size_t)grow0 * Hh + c) = hw;
                *(uint2*)(hp_out + (size_t)grow0 * Hh + c) = make_uint2(packf(w0), packf(w1));
            }
            if (v1) {
                __half2 hw; hw.x = __float2half_rn(w2); hw.y = __float2half_rn(w3);
                *(__half2*)(hh_out + (size_t)grow1 * Hh + c) = hw;
                *(uint2*)(hp_out + (size_t)grow1 * Hh + c) = make_uint2(packf(w2), packf(w3));
            }
        } else {
            if (v0) *(float2*)(f32_out + (size_t)grow0 * Hh + c) = make_float2(w0, w1);
            if (v1) *(float2*)(f32_out + (size_t)grow1 * Hh + c) = make_float2(w2, w3);
        }
    }
}

// ---------------- pooling (8-deep prefetch) ----------------
#define PT 256
__global__ void k_pool(const float* __restrict__ ne, const int* __restrict__ batch) {
    __shared__ int sbk[PT];
    int c = threadIdx.x;
    int start = blockIdx.x * PT;
    int cnt_nodes = min(PT, Nn - start);
    for (int i = c; i < cnt_nodes; i += 128) sbk[i] = batch[start + i];
    __syncthreads();
    float s = 0.f, mx = 0.f; int cnt = 0;
    int curb = sbk[0];
    int i = 0;
    for (; i + 8 <= cnt_nodes; i += 8) {
        float v[8];
#pragma unroll
        for (int j = 0; j < 8; j++)
            v[j] = __ldg(ne + (size_t)(start + i + j) * Hh + c);
#pragma unroll
        for (int j = 0; j < 8; j++) {
            int b = sbk[i + j];
            if (b != curb) {
                atomicAdd(&g_psum[curb * Hh + c], s);
                atomicMax(&g_pmax[curb * Hh + c], __float_as_int(mx));
                if (c == 0) atomicAdd(&g_pcnt[curb], cnt);
                s = 0.f; mx = 0.f; cnt = 0; curb = b;
            }
            s += v[j]; mx = fmaxf(mx, v[j]); cnt++;
        }
    }
    for (; i < cnt_nodes; i++) {
        int b = sbk[i];
        if (b != curb) {
            atomicAdd(&g_psum[curb * Hh + c], s);
            atomicMax(&g_pmax[curb * Hh + c], __float_as_int(mx));
            if (c == 0) atomicAdd(&g_pcnt[curb], cnt);
            s = 0.f; mx = 0.f; cnt = 0; curb = b;
        }
        float v = ne[(size_t)(start + i) * Hh + c];
        s += v; mx = fmaxf(mx, v); cnt++;
    }
    atomicAdd(&g_psum[curb * Hh + c], s);
    atomicMax(&g_pmax[curb * Hh + c], __float_as_int(mx));
    if (c == 0) atomicAdd(&g_pcnt[curb], cnt);
}

__global__ void k_pool_fin(float* __restrict__ out) {
    int idx = blockIdx.x * blockDim.x + threadIdx.x;
    if (idx >= Bb * Hh) return;
    int b = idx >> 7, c = idx & 127;
    int cnt_i = g_pcnt[b];
    float sum = g_psum[idx];
    int   mxi = g_pmax[idx];
    float cnt = fmaxf((float)cnt_i, 1.f);
    out[(size_t)Nn * Hh + b * 2 * Hh + c]      = sum / cnt;
    out[(size_t)Nn * Hh + b * 2 * Hh + Hh + c] = __int_as_float(mxi);
    // self-clean for next pass
    g_psum[idx] = 0.f;
    g_pmax[idx] = 0;
    if (c == 0) g_pcnt[b] = 0;
}

// ---------------- launch ----------------
extern "C" void kernel_launch(void* const* d_in, const int* in_sizes, int n_in,
                              void* d_out, int out_size) {
    const float* x    = (const float*)d_in[0];
    const int*   edge = (const int*)  d_in[1];
    const int*   batch= (const int*)  d_in[2];
    const float* W0   = (const float*)d_in[3];
    const float* b0   = (const float*)d_in[4];
    const float* g0   = (const float*)d_in[5];
    const float* be0  = (const float*)d_in[6];
    const float* Wl1  = (const float*)d_in[7];
    const float* bl1  = (const float*)d_in[8];
    const float* Wr1  = (const float*)d_in[9];
    const float* g1   = (const float*)d_in[10];
    const float* be1  = (const float*)d_in[11];
    const float* Wl2  = (const float*)d_in[12];
    const float* bl2  = (const float*)d_in[13];
    const float* Wr2  = (const float*)d_in[14];
    const float* g2   = (const float*)d_in[15];
    const float* be2  = (const float*)d_in[16];
    const float* Wl3  = (const float*)d_in[17];
    const float* bl3  = (const float*)d_in[18];
    const float* Wr3  = (const float*)d_in[19];
    const float* g3   = (const float*)d_in[20];
    const float* be3  = (const float*)d_in[21];
    float* out = (float*)d_out;

    static int attr_set = 0;
    if (!attr_set) {
        cudaFuncSetAttribute(k_gemm_mma, cudaFuncAttributeMaxDynamicSharedMemorySize, GSMEM);
        attr_set = 1;
    }

    __half* hh = 0;
    uint32_t* hp0 = 0;
    uint32_t* hp1 = 0;
    uint32_t* agp = 0;
    uint4* wf = 0;
    cudaGetSymbolAddress((void**)&hh, g_hh);
    cudaGetSymbolAddress((void**)&hp0, g_hp0);
    cudaGetSymbolAddress((void**)&hp1, g_hp1);
    cudaGetSymbolAddress((void**)&agp, g_agp);
    cudaGetSymbolAddress((void**)&wf, g_wfrag);

    int gemmGrid = (Nn + 255) / 256;
    int aggGrid  = (Nn * 32 + 255) / 256;

    // 1: embed + degree + weight prep
    k_pre     <<<PRE_GRID, 128>>>(x, W0, b0, g0, be0, hp0, edge,
                                  Wl1, Wr1, Wl2, Wr2, Wl3, Wr3);
    // 2: scan + fill (single kernel, chained lookback + grid barrier)
    k_scanfill<<<NBLK, 1024>>>(edge);
    // 3: agg layer 1 (+ state cleanup)
    k_agg     <<<aggGrid, 256>>>(hh, agp, 1);
    // 4: GEMM layer 1  <-- profiled
    k_gemm_mma<<<gemmGrid, 512, GSMEM>>>(agp, hp0, wf,
                                         bl1, g1, be1, hh, hp1, (float*)0, 0);
    // layer 2
    k_agg     <<<aggGrid, 256>>>(hh, agp, 0);
    k_gemm_mma<<<gemmGrid, 512, GSMEM>>>(agp, hp1, wf + 8192,
                                         bl2, g2, be2, hh, hp0, (float*)0, 0);
    // layer 3
    k_agg     <<<aggGrid, 256>>>(hh, agp, 0);
    k_gemm_mma<<<gemmGrid, 512, GSMEM>>>(agp, hp0, wf + 16384,
                                         bl3, g3, be3, (__half*)0, (uint32_t*)0, out, 1);

    k_pool    <<<(Nn + PT - 1) / PT, 128>>>(out, batch);
    k_pool_fin<<<(Bb * Hh + 127) / 128, 128>>>(out);
}

// round 15
// speedup vs baseline: 1.6639x; 1.6639x over previous
#include <cuda_runtime.h>
#include <cuda_bf16.h>
#include <cuda_fp16.h>
#include <cstdint>

#define Nn   100000
#define Ee   1600000
#define Bb   64
#define DINc 9
#define Hh   128
#define EPSv 1e-5f

// ---------------- device scratch ----------------
__device__ __half   g_hh [Nn * Hh];      // half features: agg gather source AND GEMM root operand
__device__ __half   g_agh[Nn * Hh];      // half aggregated features (GEMM agg operand)
__device__ uint2    g_wfrag[3 * 8192];   // per-layer fp16 mma B fragments
__device__ int      g_deg[Nn];
__device__ int      g_rowptr[Nn + 1];
__device__ int      g_rowfill[Nn];
__device__ int      g_col[Ee];
__device__ int      g_bsum[128];
__device__ float    g_psum[Bb * Hh];
__device__ int      g_pmax[Bb * Hh];
__device__ int      g_pcnt[Bb];

// ---------------- helpers ----------------
__device__ __forceinline__ uint32_t packh2(float a, float b) {
    __half2 h = __floats2half2_rn(a, b);
    return *reinterpret_cast<uint32_t*>(&h);
}
__device__ __forceinline__ void mma16816_f16(float* d, const uint32_t* a, uint32_t b0, uint32_t b1) {
    asm volatile("mma.sync.aligned.m16n8k16.row.col.f32.f16.f16.f32 "
        "{%0,%1,%2,%3}, {%4,%5,%6,%7}, {%8,%9}, {%0,%1,%2,%3};"
        : "+f"(d[0]), "+f"(d[1]), "+f"(d[2]), "+f"(d[3])
        : "r"(a[0]), "r"(a[1]), "r"(a[2]), "r"(a[3]), "r"(b0), "r"(b1));
}
__device__ __forceinline__ void acc_h4(float4& a, uint2 u) {
    __half2 p0 = *reinterpret_cast<const __half2*>(&u.x);
    __half2 p1 = *reinterpret_cast<const __half2*>(&u.y);
    float2 f0 = __half22float2(p0);
    float2 f1 = __half22float2(p1);
    a.x += f0.x; a.y += f0.y; a.z += f1.x; a.w += f1.y;
}

// ---------------- node embedder (+ global init fused) ----------------
__global__ void k_embed(const float* __restrict__ x, const float* __restrict__ W0,
                        const float* __restrict__ b0, const float* __restrict__ g0,
                        const float* __restrict__ be0) {
    int n = blockIdx.x;
    int o = threadIdx.x;
    int gid = n * 128 + o;
    if (gid < Nn) { g_deg[gid] = 0; g_rowfill[gid] = 0; }
    if (gid < Bb * Hh) { g_psum[gid] = 0.f; g_pmax[gid] = 0; }
    if (gid < Bb) g_pcnt[gid] = 0;

    __shared__ float sx[DINc];
    if (o < DINc) sx[o] = x[n * DINc + o];
    __syncthreads();
    float acc = b0[o];
#pragma unroll
    for (int k = 0; k < DINc; k++) acc += W0[o * DINc + k] * sx[k];

    float s = acc, sq = acc * acc;
#pragma unroll
    for (int ofs = 16; ofs > 0; ofs >>= 1) {
        s  += __shfl_xor_sync(0xffffffffu, s,  ofs);
        sq += __shfl_xor_sync(0xffffffffu, sq, ofs);
    }
    __shared__ float rs[4], rq[4];
    int w = o >> 5, lane = o & 31;
    if (lane == 0) { rs[w] = s; rq[w] = sq; }
    __syncthreads();
    s  = rs[0] + rs[1] + rs[2] + rs[3];
    sq = rq[0] + rq[1] + rq[2] + rq[3];
    float mean = s * (1.f / Hh);
    float var  = sq * (1.f / Hh) - mean * mean;
    float rstd = rsqrtf(var + EPSv);
    float v = (acc - mean) * rstd * g0[o] + be0[o];
    float r = fmaxf(v, 0.f);
    g_hh[(size_t)n * Hh + o] = __float2half_rn(r);
}

// ---------------- CSR build ----------------
__global__ void k_degree(const int* __restrict__ edge) {
    int e = blockIdx.x * blockDim.x + threadIdx.x;
    if (e >= Ee) return;
    atomicAdd(&g_deg[edge[Ee + e]], 1);
}

__global__ void k_scan1() {
    __shared__ int sh[1024];
    int t = threadIdx.x;
    int idx = blockIdx.x * 1024 + t;
    int v = (idx < Nn) ? g_deg[idx] : 0;
    sh[t] = v;
    for (int ofs = 1; ofs < 1024; ofs <<= 1) {
        __syncthreads();
        int add = (t >= ofs) ? sh[t - ofs] : 0;
        __syncthreads();
        sh[t] += add;
    }
    __syncthreads();
    if (idx < Nn) g_rowptr[idx] = sh[t] - v;
    if (t == 1023) g_bsum[blockIdx.x] = sh[1023];
}

__global__ void k_scan23(int nblk) {
    __shared__ int sp[128];
    int t = threadIdx.x;
    if (t < 128) sp[t] = (t < nblk) ? g_bsum[t] : 0;
    __syncthreads();
    for (int ofs = 1; ofs < 128; ofs <<= 1) {
        int add = 0;
        if (t < 128 && t >= ofs) add = sp[t - ofs];
        __syncthreads();
        if (t < 128) sp[t] += add;
        __syncthreads();
    }
    int b = blockIdx.x;
    int off = sp[b] - ((b < nblk) ? g_bsum[b] : 0);
    int idx = b * 1024 + t;
    if (idx < Nn) g_rowptr[idx] += off;
    if (idx == Nn) g_rowptr[Nn] = Ee;
}

__global__ void k_fill(const int* __restrict__ edge) {
    int e = blockIdx.x * blockDim.x + threadIdx.x;
    if (e >= Ee) return;
    int d = edge[Ee + e];
    int pos = g_rowptr[d] + atomicAdd(&g_rowfill[d], 1);
    g_col[pos] = edge[e];
}

// ---------------- mean aggregation: warp/node, 8-deep (round-8 proven loop) ----------------
__global__ void k_agg(const __half* __restrict__ hh, __half* __restrict__ agh) {
    int gw   = (blockIdx.x * blockDim.x + threadIdx.x) >> 5;
    int lane = threadIdx.x & 31;
    if (gw >= Nn) return;
    int beg = g_rowptr[gw], end = g_rowptr[gw + 1];
    float4 aA = make_float4(0.f, 0.f, 0.f, 0.f);
    float4 aB = make_float4(0.f, 0.f, 0.f, 0.f);
    float4 aC = make_float4(0.f, 0.f, 0.f, 0.f);
    float4 aD = make_float4(0.f, 0.f, 0.f, 0.f);
    int e = beg;
    for (; e + 8 <= end; e += 8) {
        int s0 = __ldg(&g_col[e]);
        int s1 = __ldg(&g_col[e + 1]);
        int s2 = __ldg(&g_col[e + 2]);
        int s3 = __ldg(&g_col[e + 3]);
        int s4 = __ldg(&g_col[e + 4]);
        int s5 = __ldg(&g_col[e + 5]);
        int s6 = __ldg(&g_col[e + 6]);
        int s7 = __ldg(&g_col[e + 7]);
        uint2 u0 = __ldg((const uint2*)(hh + (size_t)s0 * Hh) + lane);
        uint2 u1 = __ldg((const uint2*)(hh + (size_t)s1 * Hh) + lane);
        uint2 u2 = __ldg((const uint2*)(hh + (size_t)s2 * Hh) + lane);
        uint2 u3 = __ldg((const uint2*)(hh + (size_t)s3 * Hh) + lane);
        uint2 u4 = __ldg((const uint2*)(hh + (size_t)s4 * Hh) + lane);
        uint2 u5 = __ldg((const uint2*)(hh + (size_t)s5 * Hh) + lane);
        uint2 u6 = __ldg((const uint2*)(hh + (size_t)s6 * Hh) + lane);
        uint2 u7 = __ldg((const uint2*)(hh + (size_t)s7 * Hh) + lane);
        acc_h4(aA, u0); acc_h4(aB, u1); acc_h4(aC, u2); acc_h4(aD, u3);
        acc_h4(aA, u4); acc_h4(aB, u5); acc_h4(aC, u6); acc_h4(aD, u7);
    }
    for (; e + 4 <= end; e += 4) {
        int s0 = __ldg(&g_col[e]);
        int s1 = __ldg(&g_col[e + 1]);
        int s2 = __ldg(&g_col[e + 2]);
        int s3 = __ldg(&g_col[e + 3]);
        uint2 u0 = __ldg((const uint2*)(hh + (size_t)s0 * Hh) + lane);
        uint2 u1 = __ldg((const uint2*)(hh + (size_t)s1 * Hh) + lane);
        uint2 u2 = __ldg((const uint2*)(hh + (size_t)s2 * Hh) + lane);
        uint2 u3 = __ldg((const uint2*)(hh + (size_t)s3 * Hh) + lane);
        acc_h4(aA, u0); acc_h4(aB, u1); acc_h4(aC, u2); acc_h4(aD, u3);
    }
    for (; e < end; e++) {
        int s = __ldg(&g_col[e]);
        uint2 u = __ldg((const uint2*)(hh + (size_t)s * Hh) + lane);
        acc_h4(aA, u);
    }
    float inv = 1.0f / fmaxf((float)(end - beg), 1.0f);
    uint2 q;
    q.x = packh2((aA.x + aB.x + aC.x + aD.x) * inv, (aA.y + aB.y + aC.y + aD.y) * inv);
    q.y = packh2((aA.z + aB.z + aC.z + aD.z) * inv, (aA.w + aB.w + aC.w + aD.w) * inv);
    ((uint2*)(agh + (size_t)gw * Hh))[lane] = q;
}

// ---------------- weight prep (all 3 layers): [Wl|Wr] K=256 -> fp16 B fragments ----------------
__global__ void k_prepw(const float* __restrict__ Wl1, const float* __restrict__ Wr1,
                        const float* __restrict__ Wl2, const float* __restrict__ Wr2,
                        const float* __restrict__ Wl3, const float* __restrict__ Wr3) {
    int idx = blockIdx.x * blockDim.x + threadIdx.x;
    if (idx >= 3 * 8192) return;
    int L = idx >> 13, id = idx & 8191;
    const float* Wl = (L == 0) ? Wl1 : (L == 1) ? Wl2 : Wl3;
    const float* Wr = (L == 0) ? Wr1 : (L == 1) ? Wr2 : Wr3;
    int lane = id & 31, ks = (id >> 5) & 15, nt = id >> 9;
    int o = nt * 8 + (lane >> 2);
    int kb = ks * 16 + 2 * (lane & 3);
    float v[4];
#pragma unroll
    for (int j = 0; j < 4; j++) {
        int k = kb + (j >> 1) * 8 + (j & 1);   // k0, k0+1, k0+8, k0+9
        v[j] = (k < Hh) ? Wl[o * Hh + k] : Wr[o * Hh + (k - Hh)];
    }
    uint2 q;
    q.x = packh2(v[0], v[1]);
    q.y = packh2(v[2], v[3]);
    g_wfrag[idx] = q;
}

// ---------------- fp16 mma fused dual GEMM + LN + ReLU, M=256 tile ----------------
#define GSMEM (8192 * 8 + 3 * 512)

__global__ void __launch_bounds__(512, 1)
k_gemm_mma(const __half* __restrict__ agh, const __half* __restrict__ hroot,
           const uint2* __restrict__ wfrag,
           const float* __restrict__ bl, const float* __restrict__ gg,
           const float* __restrict__ bb,
           __half* __restrict__ hh_out, float* __restrict__ f32_out, int mode)
{
    extern __shared__ char smc[];
    uint2* sB    = (uint2*)smc;                       // 8192 uint2 = 64 KB
    float* sBias = (float*)(smc + 8192 * 8);
    float* sG    = sBias + 128;
    float* sBb   = sG + 128;

    int tid = threadIdx.x, lane = tid & 31, warp = tid >> 5;
    int nb = blockIdx.x * 256;

#pragma unroll
    for (int i = 0; i < 16; i++) sB[tid + i * 512] = wfrag[tid + i * 512];
    if (tid < 128) { sBias[tid] = bl[tid]; sG[tid] = gg[tid]; sBb[tid] = bb[tid]; }
    __syncthreads();

    int r0    = warp * 16 + (lane >> 2);
    int grow0 = nb + r0, grow1 = grow0 + 8;
    bool v0 = grow0 < Nn, v1 = grow1 < Nn;
    int kcol = 2 * (lane & 3);

    float acc[16][4];
#pragma unroll
    for (int nt = 0; nt < 16; nt++) {
        acc[nt][0] = 0.f; acc[nt][1] = 0.f; acc[nt][2] = 0.f; acc[nt][3] = 0.f;
    }

#pragma unroll 4
    for (int ks = 0; ks < 16; ks++) {
        const __half* pp = (ks < 8) ? agh : hroot;
        int ko = (ks & 7) * 16 + kcol;
        const __half* r0p = pp + (size_t)grow0 * Hh + ko;
        const __half* r1p = pp + (size_t)grow1 * Hh + ko;
        uint32_t a[4];
        a[0] = v0 ? __ldg((const uint32_t*)r0p)       : 0u;
        a[1] = v1 ? __ldg((const uint32_t*)r1p)       : 0u;
        a[2] = v0 ? __ldg((const uint32_t*)(r0p + 8)) : 0u;
        a[3] = v1 ? __ldg((const uint32_t*)(r1p + 8)) : 0u;
        const uint2* brow = sB + ks * 32 + lane;
#pragma unroll
        for (int nt = 0; nt < 16; nt++) {
            uint2 b = brow[nt * 512];
            mma16816_f16(acc[nt], a, b.x, b.y);
        }
    }

    // ---- epilogue: bias + LN + ReLU ----
    float s0 = 0.f, q0 = 0.f, s1 = 0.f, q1 = 0.f;
#pragma unroll
    for (int nt = 0; nt < 16; nt++) {
        int c = nt * 8 + kcol;
        float b0v = sBias[c], b1v = sBias[c + 1];
        acc[nt][0] += b0v; acc[nt][1] += b1v;
        acc[nt][2] += b0v; acc[nt][3] += b1v;
        s0 += acc[nt][0] + acc[nt][1];
        q0 += acc[nt][0] * acc[nt][0] + acc[nt][1] * acc[nt][1];
        s1 += acc[nt][2] + acc[nt][3];
        q1 += acc[nt][2] * acc[nt][2] + acc[nt][3] * acc[nt][3];
    }
#pragma unroll
    for (int ofs = 1; ofs <= 2; ofs <<= 1) {
        s0 += __shfl_xor_sync(0xffffffffu, s0, ofs);
        q0 += __shfl_xor_sync(0xffffffffu, q0, ofs);
        s1 += __shfl_xor_sync(0xffffffffu, s1, ofs);
        q1 += __shfl_xor_sync(0xffffffffu, q1, ofs);
    }
    float mean0 = s0 * (1.f / Hh);
    float rstd0 = rsqrtf(q0 * (1.f / Hh) - mean0 * mean0 + EPSv);
    float mean1 = s1 * (1.f / Hh);
    float rstd1 = rsqrtf(q1 * (1.f / Hh) - mean1 * mean1 + EPSv);

#pragma unroll
    for (int nt = 0; nt < 16; nt++) {
        int c = nt * 8 + kcol;
        float gc0 = sG[c], gc1 = sG[c + 1], bc0 = sBb[c], bc1 = sBb[c + 1];
        float w0 = fmaxf((acc[nt][0] - mean0) * rstd0 * gc0 + bc0, 0.f);
        float w1 = fmaxf((acc[nt][1] - mean0) * rstd0 * gc1 + bc1, 0.f);
        float w2 = fmaxf((acc[nt][2] - mean1) * rstd1 * gc0 + bc0, 0.f);
        float w3 = fmaxf((acc[nt][3] - mean1) * rstd1 * gc1 + bc1, 0.f);
        if (mode == 0) {
            // in-place safe: each lane reads/writes exactly its own (row, col) set
            if (v0) *(uint32_t*)(hh_out + (size_t)grow0 * Hh + c) = packh2(w0, w1);
            if (v1) *(uint32_t*)(hh_out + (size_t)grow1 * Hh + c) = packh2(w2, w3);
        } else {
            if (v0) *(float2*)(f32_out + (size_t)grow0 * Hh + c) = make_float2(w0, w1);
            if (v1) *(float2*)(f32_out + (size_t)grow1 * Hh + c) = make_float2(w2, w3);
        }
    }
}

// ---------------- pooling (8-deep prefetch) ----------------
#define PT 256
__global__ void k_pool(const float* __restrict__ ne, const int* __restrict__ batch) {
    __shared__ int sbk[PT];
    int c = threadIdx.x;
    int start = blockIdx.x * PT;
    int cnt_nodes = min(PT, Nn - start);
    for (int i = c; i < cnt_nodes; i += 128) sbk[i] = batch[start + i];
    __syncthreads();
    float s = 0.f, mx = 0.f; int cnt = 0;
    int curb = sbk[0];
    int i = 0;
    for (; i + 8 <= cnt_nodes; i += 8) {
        float v[8];
#pragma unroll
        for (int j = 0; j < 8; j++)
            v[j] = __ldg(ne + (size_t)(start + i + j) * Hh + c);
#pragma unroll
        for (int j = 0; j < 8; j++) {
            int b = sbk[i + j];
            if (b != curb) {
                atomicAdd(&g_psum[curb * Hh + c], s);
                atomicMax(&g_pmax[curb * Hh + c], __float_as_int(mx));
                if (c == 0) atomicAdd(&g_pcnt[curb], cnt);
                s = 0.f; mx = 0.f; cnt = 0; curb = b;
            }
            s += v[j]; mx = fmaxf(mx, v[j]); cnt++;
        }
    }
    for (; i < cnt_nodes; i++) {
        int b = sbk[i];
        if (b != curb) {
            atomicAdd(&g_psum[curb * Hh + c], s);
            atomicMax(&g_pmax[curb * Hh + c], __float_as_int(mx));
            if (c == 0) atomicAdd(&g_pcnt[curb], cnt);
            s = 0.f; mx = 0.f; cnt = 0; curb = b;
        }
        float v = ne[(size_t)(start + i) * Hh + c];
        s += v; mx = fmaxf(mx, v); cnt++;
    }
    atomicAdd(&g_psum[curb * Hh + c], s);
    atomicMax(&g_pmax[curb * Hh + c], __float_as_int(mx));
    if (c == 0) atomicAdd(&g_pcnt[curb], cnt);
}

__global__ void k_pool_fin(float* __restrict__ out) {
    int idx = blockIdx.x * blockDim.x + threadIdx.x;
    if (idx >= Bb * Hh) return;
    int b = idx >> 7, c = idx & 127;
    float cnt = fmaxf((float)g_pcnt[b], 1.f);
    out[(size_t)Nn * Hh + b * 2 * Hh + c]      = g_psum[idx] / cnt;
    out[(size_t)Nn * Hh + b * 2 * Hh + Hh + c] = __int_as_float(g_pmax[idx]);
}

// ---------------- launch ----------------
extern "C" void kernel_launch(void* const* d_in, const int* in_sizes, int n_in,
                              void* d_out, int out_size) {
    const float* x    = (const float*)d_in[0];
    const int*   edge = (const int*)  d_in[1];
    const int*   batch= (const int*)  d_in[2];
    const float* W0   = (const float*)d_in[3];
    const float* b0   = (const float*)d_in[4];
    const float* g0   = (const float*)d_in[5];
    const float* be0  = (const float*)d_in[6];
    const float* Wl1  = (const float*)d_in[7];
    const float* bl1  = (const float*)d_in[8];
    const float* Wr1  = (const float*)d_in[9];
    const float* g1   = (const float*)d_in[10];
    const float* be1  = (const float*)d_in[11];
    const float* Wl2  = (const float*)d_in[12];
    const float* bl2  = (const float*)d_in[13];
    const float* Wr2  = (const float*)d_in[14];
    const float* g2   = (const float*)d_in[15];
    const float* be2  = (const float*)d_in[16];
    const float* Wl3  = (const float*)d_in[17];
    const float* bl3  = (const float*)d_in[18];
    const float* Wr3  = (const float*)d_in[19];
    const float* g3   = (const float*)d_in[20];
    const float* be3  = (const float*)d_in[21];
    float* out = (float*)d_out;

    static int attr_set = 0;
    if (!attr_set) {
        cudaFuncSetAttribute(k_gemm_mma, cudaFuncAttributeMaxDynamicSharedMemorySize, GSMEM);
        attr_set = 1;
    }

    __half* hh = 0;
    __half* agh = 0;
    uint2* wf = 0;
    cudaGetSymbolAddress((void**)&hh, g_hh);
    cudaGetSymbolAddress((void**)&agh, g_agh);
    cudaGetSymbolAddress((void**)&wf, g_wfrag);

    int nblkScan = (Nn + 1023) / 1024;
    int gemmGrid = (Nn + 255) / 256;
    int aggGrid  = (Nn * 32 + 255) / 256;
    int prepGrid = (3 * 8192 + 255) / 256;

    k_embed <<<Nn, 128>>>(x, W0, b0, g0, be0);
    k_degree<<<(Ee + 255) / 256, 256>>>(edge);
    k_scan1 <<<nblkScan, 1024>>>();
    k_scan23<<<nblkScan, 1024>>>(nblkScan);
    k_fill  <<<(Ee + 255) / 256, 256>>>(edge);
    k_prepw <<<prepGrid, 256>>>(Wl1, Wr1, Wl2, Wr2, Wl3, Wr3);

    // layer 1: agg(hh)->agh; gemm(agh, hh) -> hh (in-place)
    k_agg   <<<aggGrid, 256>>>(hh, agh);
    k_gemm_mma<<<gemmGrid, 512, GSMEM>>>(agh, hh, wf,
                                         bl1, g1, be1, hh, (float*)0, 0);
    // layer 2
    k_agg   <<<aggGrid, 256>>>(hh, agh);
    k_gemm_mma<<<gemmGrid, 512, GSMEM>>>(agh, hh, wf + 8192,
                                         bl2, g2, be2, hh, (float*)0, 0);
    // layer 3 -> fp32 out
    k_agg   <<<aggGrid, 256>>>(hh, agh);
    k_gemm_mma<<<gemmGrid, 512, GSMEM>>>(agh, hh, wf + 16384,
                                         bl3, g3, be3, (__half*)0, out, 1);

    k_pool    <<<(Nn + PT - 1) / PT, 128>>>(out, batch);
    k_pool_fin<<<(Bb * Hh + 127) / 128, 128>>>(out);
}